// round 7
// baseline (speedup 1.0000x reference)
#include <cuda_runtime.h>
#include <cuda_bf16.h>
#include <math.h>
#include <stdint.h>

#define BB   1024
#define NSEQ 60
#define FF   1024
#define NN   120   // 2*NSEQ

// Output layout (flattened tuple, fp32):
// x(B,2,2048) o1(B,2,1024) o2 h1 h2 ATT1(B,60,1) ATT2 att11(B,60) att22 att12 att21
#define OFF_X    0ull
#define OFF_O1   4194304ull
#define OFF_O2   6291456ull
#define OFF_H1   8388608ull
#define OFF_H2   10485760ull
#define OFF_ATT1 12582912ull
#define OFF_ATT2 12644352ull
#define OFF_A11  12705792ull
#define OFF_A22  12767232ull
#define OFF_A12  12828672ull
#define OFF_A21  12890112ull

// Scratch
static __device__ __nv_bfloat16 g_thh[4096 * 1024];  // tanh(h) hi
static __device__ __nv_bfloat16 g_thl[4096 * 1024];  // tanh(h) lo
static __device__ __nv_bfloat16 g_qwh[1024 * 1024];  // q_w hi
static __device__ __nv_bfloat16 g_qwl[1024 * 1024];  // q_w lo
static __device__ float         g_qm[4096 * 1024];   // qm

// pipeline counters (zeroed by k_split_w each call)
static __device__ int g_sel_cnt[32];
static __device__ int g_qm_cnt[32];

typedef unsigned int uint32;
#define FULLW 0xffffffffu

__device__ __forceinline__ float dot4(float4 a, float4 b) {
    return a.x * b.x + a.y * b.y + a.z * b.z + a.w * b.w;
}

__device__ __forceinline__ void split4(float4 v, uint2& uh, uint2& ul) {
    __nv_bfloat16 h0 = __float2bfloat16_rn(v.x);
    __nv_bfloat16 h1 = __float2bfloat16_rn(v.y);
    __nv_bfloat16 h2 = __float2bfloat16_rn(v.z);
    __nv_bfloat16 h3 = __float2bfloat16_rn(v.w);
    __nv_bfloat16 l0 = __float2bfloat16_rn(v.x - __bfloat162float(h0));
    __nv_bfloat16 l1 = __float2bfloat16_rn(v.y - __bfloat162float(h1));
    __nv_bfloat16 l2 = __float2bfloat16_rn(v.z - __bfloat162float(h2));
    __nv_bfloat16 l3 = __float2bfloat16_rn(v.w - __bfloat162float(h3));
    uh.x = ((uint32)__bfloat16_as_ushort(h1) << 16) | __bfloat16_as_ushort(h0);
    uh.y = ((uint32)__bfloat16_as_ushort(h3) << 16) | __bfloat16_as_ushort(h2);
    ul.x = ((uint32)__bfloat16_as_ushort(l1) << 16) | __bfloat16_as_ushort(l0);
    ul.y = ((uint32)__bfloat16_as_ushort(l3) << 16) | __bfloat16_as_ushort(l2);
}

__device__ __forceinline__ void cpa16(uint32 dst, const void* src) {
    asm volatile("cp.async.cg.shared.global [%0], [%1], 16;" :: "r"(dst), "l"(src));
}
__device__ __forceinline__ void ldsm4(uint32* r, uint32 addr) {
    asm volatile("ldmatrix.sync.aligned.m8n8.x4.shared.b16 {%0,%1,%2,%3}, [%4];"
                 : "=r"(r[0]), "=r"(r[1]), "=r"(r[2]), "=r"(r[3]) : "r"(addr));
}
__device__ __forceinline__ void mma_bf16(float* c, const uint32* a, uint32 b0, uint32 b1) {
    asm volatile(
        "mma.sync.aligned.m16n8k16.row.col.f32.bf16.bf16.f32 "
        "{%0,%1,%2,%3}, {%4,%5,%6,%7}, {%8,%9}, {%0,%1,%2,%3};"
        : "+f"(c[0]), "+f"(c[1]), "+f"(c[2]), "+f"(c[3])
        : "r"(a[0]), "r"(a[1]), "r"(a[2]), "r"(a[3]), "r"(b0), "r"(b1));
}

// release/acquire over device counters (threadFenceReduction pattern)
__device__ __forceinline__ void release_cnt(int* cnt) {
    __threadfence();
    __syncthreads();
    if (threadIdx.x == 0) atomicAdd(cnt, 1);
}
__device__ __forceinline__ void acquire_cnt(int* cnt, int target) {
    if (threadIdx.x == 0) {
        while (atomicAdd(cnt, 0) < target) __nanosleep(128);
    }
    __syncthreads();
    __threadfence();
}

// ---------------------------------------------------------------------------
// K0: split q_w into bf16 hi/lo + zero pipeline counters
// ---------------------------------------------------------------------------
__global__ __launch_bounds__(256) void k_split_w(const float* __restrict__ qw)
{
    if (blockIdx.x == 0 && threadIdx.x < 64) {
        if (threadIdx.x < 32) g_sel_cnt[threadIdx.x] = 0;
        else                  g_qm_cnt[threadIdx.x - 32] = 0;
    }
    int idx = blockIdx.x * 256 + threadIdx.x;
    float4 v = ((const float4*)qw)[idx];
    uint2 uh, ul;
    split4(v, uh, ul);
    *(uint2*)(g_qwh + 4 * (size_t)idx) = uh;
    *(uint2*)(g_qwl + 4 * (size_t)idx) = ul;
}

// ---------------------------------------------------------------------------
// Fused pipeline kernel. Group g = 32 batches. Per group (128 CTAs):
//   r in [0,64):   select CTA, batch = g*32 + (r>>1), which = r&1
//   r in [64,96):  qm GEMM tile M64xN64, q = r-64: m0 = g*128 + (q>>4)*64,
//                  n0 = (q&15)*64 ; waits sel_cnt[g]==64
//   r in [96,128): attend CTA, batch = g*32 + (r-96); waits qm_cnt[g]==32
// ---------------------------------------------------------------------------
#define GSZ 128

// qm tile smem: 3 stages x (4 arrays x 64 rows x 48B) = 36864
#define QT_ROWB 48
#define QT_ARR  3072
#define QT_STAGE 12288
// attend smem layout
#define AT_L    0
#define AT_SS   65536
#define AT_RED  67456
#define FUSED_SMEM 67968

__device__ void role_select(
    const float* __restrict__ x1, const float* __restrict__ x2,
    const float* __restrict__ fc_w, float* __restrict__ out,
    unsigned char* smem, int b, int which, int gid)
{
    float4* s_fw = (float4*)smem;                  // 512 float4
    float*  s_log = (float*)(smem + 8192);         // 2*64
    int*    s_idx = (int*)(smem + 8704);           // 2

    const float* x = which ? x2 : x1;
    const float4* x4 = (const float4*)(x + (size_t)b * NSEQ * FF);
    const int tid = threadIdx.x;
    const int w = tid >> 5, lane = tid & 31;

    const float4* fw4 = (const float4*)fc_w;
    s_fw[tid] = fw4[tid];
    s_fw[tid + 256] = fw4[tid + 256];
    __syncthreads();

    for (int n = w; n < NSEQ; n += 8) {
        const float4* row = x4 + n * 256;
        float p0 = 0.f, p1 = 0.f;
#pragma unroll
        for (int i = 0; i < 8; i++) {
            float4 v = row[lane + 32 * i];
            p0 += dot4(v, s_fw[lane + 32 * i]);
            p1 += dot4(v, s_fw[256 + lane + 32 * i]);
        }
#pragma unroll
        for (int off = 16; off; off >>= 1) {
            p0 += __shfl_down_sync(FULLW, p0, off);
            p1 += __shfl_down_sync(FULLW, p1, off);
        }
        if (lane == 0) { s_log[n] = p0; s_log[64 + n] = p1; }
    }
    __syncthreads();

    if (tid < 2) {
        float best = s_log[tid * 64];
        int bi = 0;
        for (int n = 1; n < NSEQ; n++) {
            float v = s_log[tid * 64 + n];
            if (v > best) { best = v; bi = n; }
        }
        s_idx[tid] = bi;
    }
    __syncthreads();

    const int i0 = s_idx[0], i1 = s_idx[1];
    float4* h4 = (float4*)(out + (which ? OFF_H2 : OFF_H1) + (size_t)b * 2 * FF);
    const size_t row0 = ((size_t)b * 4 + which * 2) * FF;

    float4 v = x4[i0 * 256 + tid];
    h4[tid] = v;
    float4 t0 = make_float4(tanhf(v.x), tanhf(v.y), tanhf(v.z), tanhf(v.w));
    uint2 uh, ul;
    split4(t0, uh, ul);
    *(uint2*)(g_thh + row0 + 4 * tid) = uh;
    *(uint2*)(g_thl + row0 + 4 * tid) = ul;

    v = x4[i1 * 256 + tid];
    h4[256 + tid] = v;
    float4 t1 = make_float4(tanhf(v.x), tanhf(v.y), tanhf(v.z), tanhf(v.w));
    split4(t1, uh, ul);
    *(uint2*)(g_thh + row0 + FF + 4 * tid) = uh;
    *(uint2*)(g_thl + row0 + FF + 4 * tid) = ul;

    release_cnt(&g_sel_cnt[gid]);
}

__device__ void role_qm(const float* __restrict__ qb,
                        unsigned char* smem, int m0, int n0, int gid)
{
    const int tid = threadIdx.x;
    const int lane = tid & 31;
    const int wid = tid >> 5;
    const int warp_m = wid >> 1;   // 0..3 -> 16 rows each
    const int warp_n = wid & 1;    // 0..1 -> 32 cols each

    acquire_cnt(&g_sel_cnt[gid], 64);

    const uint32 sbase = (uint32)__cvta_generic_to_shared(smem);

    // fill indices: 512 chunks of 16B per stage; thread t -> chunks 2t, 2t+1
    const int c0 = tid * 2;
    const int arr0 = c0 >> 7;              // same array for both chunks
    const int w0 = c0 & 127;
    const int lrow = w0 >> 1;              // both chunks same row
    // chunk ch = 0,1 within row
    const __nv_bfloat16* srcbase;
    if (arr0 == 0)      srcbase = g_thh + (size_t)(m0 + lrow) * 1024;
    else if (arr0 == 1) srcbase = g_thl + (size_t)(m0 + lrow) * 1024;
    else if (arr0 == 2) srcbase = g_qwh + (size_t)(n0 + lrow) * 1024;
    else                srcbase = g_qwl + (size_t)(n0 + lrow) * 1024;
    const uint32 dst0 = arr0 * QT_ARR + lrow * QT_ROWB;

    const int ag = lane >> 3;
    const uint32 a_off = (warp_m * 16 + (lane & 7) + (ag & 1) * 8) * QT_ROWB + (ag >> 1) * 16;
    const uint32 b_off = (warp_n * 32 + (lane & 7) + ((lane >> 4) & 1) * 8) * QT_ROWB
                         + ((lane >> 3) & 1) * 16;

    float c[4][4];
#pragma unroll
    for (int nt = 0; nt < 4; nt++)
#pragma unroll
        for (int i = 0; i < 4; i++) c[nt][i] = 0.f;

#pragma unroll
    for (int s = 0; s < 2; s++) {
        const uint32 st = s * QT_STAGE;
        cpa16(sbase + st + dst0,      srcbase + s * 16);
        cpa16(sbase + st + dst0 + 16, srcbase + s * 16 + 8);
        asm volatile("cp.async.commit_group;");
    }

    int cur_s = 0, nxt_s = 2;
    for (int it = 0; it < 64; it++) {
        const uint32 cur = cur_s * QT_STAGE;
        asm volatile("cp.async.wait_group 1;");
        __syncthreads();

        if (it < 62) {
            const uint32 nxt = nxt_s * QT_STAGE;
            cpa16(sbase + nxt + dst0,      srcbase + (it + 2) * 16);
            cpa16(sbase + nxt + dst0 + 16, srcbase + (it + 2) * 16 + 8);
            asm volatile("cp.async.commit_group;");
        } else {
            asm volatile("cp.async.commit_group;");
        }

        uint32 ah[4], al[4];
        ldsm4(ah, sbase + cur + a_off);
        ldsm4(al, sbase + cur + QT_ARR + a_off);
#pragma unroll
        for (int p = 0; p < 2; p++) {
            uint32 bh[4], bl[4];
            ldsm4(bh, sbase + cur + 2 * QT_ARR + b_off + p * 16 * QT_ROWB);
            ldsm4(bl, sbase + cur + 3 * QT_ARR + b_off + p * 16 * QT_ROWB);
            mma_bf16(c[2 * p],     ah, bh[0], bh[1]);
            mma_bf16(c[2 * p],     ah, bl[0], bl[1]);
            mma_bf16(c[2 * p],     al, bh[0], bh[1]);
            mma_bf16(c[2 * p + 1], ah, bh[2], bh[3]);
            mma_bf16(c[2 * p + 1], ah, bl[2], bl[3]);
            mma_bf16(c[2 * p + 1], al, bh[2], bh[3]);
        }
        cur_s = (cur_s == 2) ? 0 : cur_s + 1;
        nxt_s = (nxt_s == 2) ? 0 : nxt_s + 1;
    }

    const int mg = m0 + warp_m * 16 + (lane >> 2);
#pragma unroll
    for (int nt = 0; nt < 4; nt++) {
        const int ng = n0 + warp_n * 32 + nt * 8 + 2 * (lane & 3);
        const float b0 = __ldg(qb + ng), b1 = __ldg(qb + ng + 1);
        *(float2*)(g_qm + (size_t)mg * 1024 + ng) =
            make_float2(c[nt][0] + b0, c[nt][1] + b1);
        *(float2*)(g_qm + (size_t)(mg + 8) * 1024 + ng) =
            make_float2(c[nt][2] + b0, c[nt][3] + b1);
    }

    release_cnt(&g_qm_cnt[gid]);
}

__device__ void role_attend(
    const float* __restrict__ x1, const float* __restrict__ x2,
    float* __restrict__ out, unsigned char* smem, int b, int gid)
{
    float4* s_L  = (float4*)(smem + AT_L);
    float (*s_s)[4] = (float (*)[4])(smem + AT_SS);
    float (*s_red)[16] = (float (*)[16])(smem + AT_RED);

    const int tid = threadIdx.x;
    const int w = tid >> 5, lane = tid & 31;
    const uint32 sL = (uint32)__cvta_generic_to_shared(s_L);

    const float* x1b = x1 + (size_t)b * NSEQ * FF;
    const float* x2b = x2 + (size_t)b * NSEQ * FF;
    const float4* qmg = (const float4*)(g_qm + (size_t)b * 4 * FF);

#define AT_ISSUE(bt)                                                          \
    {                                                                         \
        const int _st = (bt) & 3;                                             \
        _Pragma("unroll")                                                     \
        for (int _r = 0; _r < 4; _r++) {                                      \
            int _n = (bt) * 4 + _r;                                           \
            const float* _src = (_n < NSEQ) ? (x1b + (size_t)_n * FF)         \
                                            : (x2b + (size_t)(_n - NSEQ) * FF); \
            cpa16(sL + ((_st * 4 + _r) * 256 + tid) * 16, _src + 4 * tid);    \
        }                                                                     \
        asm volatile("cp.async.commit_group;");                               \
    }

    // prefetch x (input only, no dependency) BEFORE acquiring qm
    AT_ISSUE(0); AT_ISSUE(1); AT_ISSUE(2);

    acquire_cnt(&g_qm_cnt[gid], 32);

    float4 qm[4];
#pragma unroll
    for (int j = 0; j < 4; j++) qm[j] = __ldcg(qmg + j * 256 + tid);

    float4 o[4];
#pragma unroll
    for (int j = 0; j < 4; j++) o[j] = make_float4(0.f, 0.f, 0.f, 0.f);

    float l_run = 0.f;
    const float scale = 0.03125f;

    for (int bt = 0; bt < 30; bt++) {
        asm volatile("cp.async.wait_group 2;");
        __syncthreads();

        const int st = bt & 3;
        float4 rv[4];
#pragma unroll
        for (int r = 0; r < 4; r++) rv[r] = s_L[(st * 4 + r) * 256 + tid];

        if (bt + 3 < 30) { AT_ISSUE(bt + 3); }
        else { asm volatile("cp.async.commit_group;"); }

        float p[16];
#pragma unroll
        for (int r = 0; r < 4; r++)
#pragma unroll
            for (int j = 0; j < 4; j++) p[r * 4 + j] = dot4(rv[r], qm[j]);

#pragma unroll
        for (int v = 0; v < 16; v++) p[v] += __shfl_xor_sync(FULLW, p[v], 16);
        float q8[8];
#pragma unroll
        for (int v = 0; v < 8; v++) q8[v] = (lane & 16) ? p[v + 8] : p[v];
#pragma unroll
        for (int v = 0; v < 8; v++) q8[v] += __shfl_xor_sync(FULLW, q8[v], 8);
        float q4[4];
#pragma unroll
        for (int v = 0; v < 4; v++) q4[v] = (lane & 8) ? q8[v + 4] : q8[v];
#pragma unroll
        for (int v = 0; v < 4; v++) q4[v] += __shfl_xor_sync(FULLW, q4[v], 4);
        float q2[2];
#pragma unroll
        for (int v = 0; v < 2; v++) q2[v] = (lane & 4) ? q4[v + 2] : q4[v];
#pragma unroll
        for (int v = 0; v < 2; v++) q2[v] += __shfl_xor_sync(FULLW, q2[v], 2);
        float q1 = (lane & 2) ? q2[1] : q2[0];
        q1 += __shfl_xor_sync(FULLW, q1, 1);

        if (!(lane & 1)) s_red[w][lane >> 1] = q1;
        __syncthreads();

        float v16 = 0.f;
        if (lane < 16) {
#pragma unroll
            for (int ww = 0; ww < 8; ww++) v16 += s_red[ww][lane];
            v16 *= scale;
        }
        if (w == 0 && lane < 16) s_s[bt * 4 + (lane >> 2)][lane & 3] = v16;

        const int j = lane & 3;
        float t0 = __shfl_sync(FULLW, v16, j);
        float t1 = __shfl_sync(FULLW, v16, 4 + j);
        float t2 = __shfl_sync(FULLW, v16, 8 + j);
        float t3 = __shfl_sync(FULLW, v16, 12 + j);

        float w0 = __expf(t0);
        float w1 = __expf(t1);
        float w2 = __expf(t2);
        float w3 = __expf(t3);
        l_run += (w0 + w1) + (w2 + w3);

#pragma unroll
        for (int r = 0; r < 4; r++) {
            float wr = (r == 0) ? w0 : (r == 1) ? w1 : (r == 2) ? w2 : w3;
            float wa = __shfl_sync(FULLW, wr, 0);
            float wb = __shfl_sync(FULLW, wr, 1);
            float wc = __shfl_sync(FULLW, wr, 2);
            float wd = __shfl_sync(FULLW, wr, 3);
            o[0].x += wa * rv[r].x; o[0].y += wa * rv[r].y; o[0].z += wa * rv[r].z; o[0].w += wa * rv[r].w;
            o[1].x += wb * rv[r].x; o[1].y += wb * rv[r].y; o[1].z += wb * rv[r].z; o[1].w += wb * rv[r].w;
            o[2].x += wc * rv[r].x; o[2].y += wc * rv[r].y; o[2].z += wc * rv[r].z; o[2].w += wc * rv[r].w;
            o[3].x += wd * rv[r].x; o[3].y += wd * rv[r].y; o[3].z += wd * rv[r].z; o[3].w += wd * rv[r].w;
        }
    }
    __syncthreads();

    float linv[4];
#pragma unroll
    for (int j = 0; j < 4; j++) linv[j] = 1.f / __shfl_sync(FULLW, l_run, j);

#pragma unroll
    for (int j = 0; j < 4; j++) {
        float4 val;
        val.x = 0.9f * o[j].x * linv[j] + 0.1f * qm[j].x;
        val.y = 0.9f * o[j].y * linv[j] + 0.1f * qm[j].y;
        val.z = 0.9f * o[j].z * linv[j] + 0.1f * qm[j].z;
        val.w = 0.9f * o[j].w * linv[j] + 0.1f * qm[j].w;
        if (j < 2) {
            *(float4*)(out + OFF_O1 + ((size_t)b * 2 + j) * FF + 4 * tid) = val;
            *(float4*)(out + OFF_X + ((size_t)b * 2 + j) * 2048 + 4 * tid) = val;
        } else {
            *(float4*)(out + OFF_O2 + ((size_t)b * 2 + (j - 2)) * FF + 4 * tid) = val;
            *(float4*)(out + OFF_X + ((size_t)b * 2 + (j - 2)) * 2048 + 1024 + 4 * tid) = val;
        }
    }

    if (tid < NN) {
        int n = tid;
        float s0 = s_s[n][0], s1 = s_s[n][1], s2 = s_s[n][2], s3 = s_s[n][3];
        if (n < NSEQ) {
            out[OFF_ATT1 + (size_t)b * 60 + n] = __expf(s0) * linv[0];
            out[OFF_A11 + (size_t)b * 60 + n]  = __expf(s1) * linv[1];
            out[OFF_A21 + (size_t)b * 60 + n]  = __expf(s3) * linv[3];
        } else {
            int nn = n - NSEQ;
            out[OFF_ATT2 + (size_t)b * 60 + nn] = __expf(s2) * linv[2];
            out[OFF_A12 + (size_t)b * 60 + nn]  = __expf(s1) * linv[1];
            out[OFF_A22 + (size_t)b * 60 + nn]  = __expf(s3) * linv[3];
        }
    }
#undef AT_ISSUE
}

__global__ __launch_bounds__(256, 3) void k_fused(
    const float* __restrict__ x1, const float* __restrict__ x2,
    const float* __restrict__ fc_w, const float* __restrict__ qb,
    float* __restrict__ out)
{
    extern __shared__ __align__(128) unsigned char smem[];
    const int gid = blockIdx.x / GSZ;
    const int r   = blockIdx.x % GSZ;

    if (r < 64) {
        role_select(x1, x2, fc_w, out, smem, gid * 32 + (r >> 1), r & 1, gid);
    } else if (r < 96) {
        const int q = r - 64;
        role_qm(qb, smem, gid * 128 + (q >> 4) * 64, (q & 15) * 64, gid);
    } else {
        role_attend(x1, x2, out, smem, gid * 32 + (r - 96), gid);
    }
}

// ---------------------------------------------------------------------------
extern "C" void kernel_launch(void* const* d_in, const int* in_sizes, int n_in,
                              void* d_out, int out_size)
{
    (void)in_sizes; (void)n_in; (void)out_size;
    const float* x1   = (const float*)d_in[0];
    const float* x2   = (const float*)d_in[1];
    const float* fc_w = (const float*)d_in[2];
    // d_in[3] = fc_b (constant per class: doesn't change argmax over n)
    const float* q_w  = (const float*)d_in[4];
    const float* q_b  = (const float*)d_in[5];
    float* out = (float*)d_out;

    k_split_w<<<1024, 256>>>(q_w);

    cudaFuncSetAttribute(k_fused, cudaFuncAttributeMaxDynamicSharedMemorySize,
                         FUSED_SMEM);
    k_fused<<<32 * GSZ, 256, FUSED_SMEM>>>(x1, x2, fc_w, q_b, out);
}

// round 8
// speedup vs baseline: 2.5195x; 2.5195x over previous
#include <cuda_runtime.h>
#include <cuda_fp16.h>
#include <math.h>
#include <stdint.h>

#define BB   1024
#define NSEQ 60
#define FF   1024
#define NN   120   // 2*NSEQ

// Output layout (flattened tuple, fp32):
// x(B,2,2048) o1(B,2,1024) o2 h1 h2 ATT1(B,60,1) ATT2 att11(B,60) att22 att12 att21
#define OFF_X    0ull
#define OFF_O1   4194304ull
#define OFF_O2   6291456ull
#define OFF_H1   8388608ull
#define OFF_H2   10485760ull
#define OFF_ATT1 12582912ull
#define OFF_ATT2 12644352ull
#define OFF_A11  12705792ull
#define OFF_A22  12767232ull
#define OFF_A12  12828672ull
#define OFF_A21  12890112ull

// Scratch (fp16 split: A = th hi only; B = q_w hi+lo)
static __device__ __half g_thh[4096 * 1024];   // tanh(h) fp16
static __device__ __half g_qwh[1024 * 1024];   // q_w hi
static __device__ __half g_qwl[1024 * 1024];   // q_w lo
static __device__ float  g_qm[4096 * 1024];    // qm

typedef unsigned int uint32;
#define FULLW 0xffffffffu

__device__ __forceinline__ float dot4(float4 a, float4 b) {
    return a.x * b.x + a.y * b.y + a.z * b.z + a.w * b.w;
}

// pack 4 floats -> 4 fp16 (rn) in a uint2
__device__ __forceinline__ uint2 h4(float4 v) {
    __half2 a = __floats2half2_rn(v.x, v.y);
    __half2 b = __floats2half2_rn(v.z, v.w);
    uint2 r;
    r.x = *reinterpret_cast<uint32*>(&a);
    r.y = *reinterpret_cast<uint32*>(&b);
    return r;
}

__device__ __forceinline__ void cpa16(uint32 dst, const void* src) {
    asm volatile("cp.async.cg.shared.global [%0], [%1], 16;" :: "r"(dst), "l"(src));
}
__device__ __forceinline__ void ldsm4(uint32* r, uint32 addr) {
    asm volatile("ldmatrix.sync.aligned.m8n8.x4.shared.b16 {%0,%1,%2,%3}, [%4];"
                 : "=r"(r[0]), "=r"(r[1]), "=r"(r[2]), "=r"(r[3]) : "r"(addr));
}
__device__ __forceinline__ void mma_f16(float* c, const uint32* a, uint32 b0, uint32 b1) {
    asm volatile(
        "mma.sync.aligned.m16n8k16.row.col.f32.f16.f16.f32 "
        "{%0,%1,%2,%3}, {%4,%5,%6,%7}, {%8,%9}, {%0,%1,%2,%3};"
        : "+f"(c[0]), "+f"(c[1]), "+f"(c[2]), "+f"(c[3])
        : "r"(a[0]), "r"(a[1]), "r"(a[2]), "r"(a[3]), "r"(b0), "r"(b1));
}

// ---------------------------------------------------------------------------
// K0: split q_w into fp16 hi/lo
// ---------------------------------------------------------------------------
__global__ __launch_bounds__(256) void k_split_w(const float* __restrict__ qw)
{
    int idx = blockIdx.x * 256 + threadIdx.x;
    float4 v = ((const float4*)qw)[idx];
    __half hx = __float2half_rn(v.x), hy = __float2half_rn(v.y);
    __half hz = __float2half_rn(v.z), hw = __float2half_rn(v.w);
    float4 lo = make_float4(v.x - __half2float(hx), v.y - __half2float(hy),
                            v.z - __half2float(hz), v.w - __half2float(hw));
    uint2 uh;
    {
        __half2 a = __halves2half2(hx, hy);
        __half2 b = __halves2half2(hz, hw);
        uh.x = *reinterpret_cast<uint32*>(&a);
        uh.y = *reinterpret_cast<uint32*>(&b);
    }
    *(uint2*)(g_qwh + 4 * (size_t)idx) = uh;
    *(uint2*)(g_qwl + 4 * (size_t)idx) = h4(lo);
}

// ---------------------------------------------------------------------------
// K1: logits = x @ fc_w.T ; argmax ; gather h ; write h + fp16(tanh(h))
// ---------------------------------------------------------------------------
__global__ __launch_bounds__(256) void k_select(
    const float* __restrict__ x1, const float* __restrict__ x2,
    const float* __restrict__ fc_w, float* __restrict__ out)
{
    const int b = blockIdx.x;
    const int which = blockIdx.y;
    const float* x = which ? x2 : x1;
    const float4* x4 = (const float4*)(x + (size_t)b * NSEQ * FF);

    const int tid = threadIdx.x;
    const int w = tid >> 5, lane = tid & 31;

    __shared__ float4 s_fw[512];
    __shared__ float s_log[2][64];
    __shared__ int s_idx[2];

    const float4* fw4 = (const float4*)fc_w;
    s_fw[tid] = fw4[tid];
    s_fw[tid + 256] = fw4[tid + 256];
    __syncthreads();

    for (int n = w; n < NSEQ; n += 8) {
        const float4* row = x4 + n * 256;
        float p0 = 0.f, p1 = 0.f;
#pragma unroll
        for (int i = 0; i < 8; i++) {
            float4 v = row[lane + 32 * i];
            p0 += dot4(v, s_fw[lane + 32 * i]);
            p1 += dot4(v, s_fw[256 + lane + 32 * i]);
        }
#pragma unroll
        for (int off = 16; off; off >>= 1) {
            p0 += __shfl_down_sync(FULLW, p0, off);
            p1 += __shfl_down_sync(FULLW, p1, off);
        }
        if (lane == 0) { s_log[0][n] = p0; s_log[1][n] = p1; }
    }
    __syncthreads();

    if (tid < 2) {
        float best = s_log[tid][0];
        int bi = 0;
        for (int n = 1; n < NSEQ; n++) {
            float v = s_log[tid][n];
            if (v > best) { best = v; bi = n; }
        }
        s_idx[tid] = bi;
    }
    __syncthreads();

    const int i0 = s_idx[0], i1 = s_idx[1];
    float4* h4o = (float4*)(out + (which ? OFF_H2 : OFF_H1) + (size_t)b * 2 * FF);
    const size_t row0 = ((size_t)b * 4 + which * 2) * FF;

    float4 v = x4[i0 * 256 + tid];
    h4o[tid] = v;
    float4 t0 = make_float4(tanhf(v.x), tanhf(v.y), tanhf(v.z), tanhf(v.w));
    *(uint2*)(g_thh + row0 + 4 * tid) = h4(t0);

    v = x4[i1 * 256 + tid];
    h4o[256 + tid] = v;
    float4 t1 = make_float4(tanhf(v.x), tanhf(v.y), tanhf(v.z), tanhf(v.w));
    *(uint2*)(g_thh + row0 + FF + 4 * tid) = h4(t1);
}

// ---------------------------------------------------------------------------
// K2: qm = th_h @ (q_w hi + lo).T + q_b -- 2-pass fp16 tensor-core GEMM.
// BM=BN=128, BK=16, 8 warps (4m x 2n), 3-stage cp.async, wait_group 1.
// Stage = 3 arrays (AH, BH, BL) x 128 rows x 48B = 18432 B.
// ---------------------------------------------------------------------------
#define QM_ROWB 48
#define QM_AH 0
#define QM_BH 6144
#define QM_BL 12288
#define QM_STAGE_BYTES 18432
#define QM_SMEM (3 * QM_STAGE_BYTES)

__global__ __launch_bounds__(256, 2) void k_qm_mma(const float* __restrict__ qb)
{
    extern __shared__ __align__(128) unsigned char smem[];

    const int tid = threadIdx.x;
    const int lane = tid & 31;
    const int wid = tid >> 5;
    const int warp_m = wid >> 1;
    const int warp_n = wid & 1;
    const int m0 = blockIdx.y * 128;
    const int n0 = blockIdx.x * 128;

    const uint32 sbase = (uint32)__cvta_generic_to_shared(smem);

    const int lrow = tid >> 1;          // 0..127
    const int lch  = tid & 1;           // 16B chunk in row
    const uint32 ldst = lrow * QM_ROWB + lch * 16;

    const int ag = lane >> 3;
    const uint32 a_off = (warp_m * 32 + (lane & 7) + (ag & 1) * 8) * QM_ROWB + (ag >> 1) * 16;
    const uint32 b_off = (warp_n * 64 + (lane & 7) + ((lane >> 4) & 1) * 8) * QM_ROWB
                         + ((lane >> 3) & 1) * 16;

    float c[2][8][4];
#pragma unroll
    for (int mt = 0; mt < 2; mt++)
#pragma unroll
        for (int nt = 0; nt < 8; nt++)
#pragma unroll
            for (int i = 0; i < 4; i++) c[mt][nt][i] = 0.f;

#pragma unroll
    for (int s = 0; s < 2; s++) {
        const uint32 st = s * QM_STAGE_BYTES;
        const size_t ka = (size_t)(m0 + lrow) * 1024 + s * 16 + lch * 8;
        const size_t kb = (size_t)(n0 + lrow) * 1024 + s * 16 + lch * 8;
        cpa16(sbase + st + QM_AH + ldst, g_thh + ka);
        cpa16(sbase + st + QM_BH + ldst, g_qwh + kb);
        cpa16(sbase + st + QM_BL + ldst, g_qwl + kb);
        asm volatile("cp.async.commit_group;");
    }

    int cur_s = 0, nxt_s = 2;
    for (int it = 0; it < 64; it++) {
        const uint32 cur = cur_s * QM_STAGE_BYTES;
        asm volatile("cp.async.wait_group 1;");
        __syncthreads();

        if (it < 62) {
            const uint32 nxt = nxt_s * QM_STAGE_BYTES;
            const size_t ka = (size_t)(m0 + lrow) * 1024 + (it + 2) * 16 + lch * 8;
            const size_t kb = (size_t)(n0 + lrow) * 1024 + (it + 2) * 16 + lch * 8;
            cpa16(sbase + nxt + QM_AH + ldst, g_thh + ka);
            cpa16(sbase + nxt + QM_BH + ldst, g_qwh + kb);
            cpa16(sbase + nxt + QM_BL + ldst, g_qwl + kb);
            asm volatile("cp.async.commit_group;");
        } else {
            asm volatile("cp.async.commit_group;");
        }

        uint32 ah[2][4];
#pragma unroll
        for (int mt = 0; mt < 2; mt++)
            ldsm4(ah[mt], sbase + cur + QM_AH + a_off + mt * 16 * QM_ROWB);
#pragma unroll
        for (int p = 0; p < 4; p++) {
            uint32 bh[4], bl[4];
            ldsm4(bh, sbase + cur + QM_BH + b_off + p * 16 * QM_ROWB);
            ldsm4(bl, sbase + cur + QM_BL + b_off + p * 16 * QM_ROWB);
#pragma unroll
            for (int mt = 0; mt < 2; mt++) {
                mma_f16(c[mt][2 * p],     ah[mt], bh[0], bh[1]);
                mma_f16(c[mt][2 * p],     ah[mt], bl[0], bl[1]);
                mma_f16(c[mt][2 * p + 1], ah[mt], bh[2], bh[3]);
                mma_f16(c[mt][2 * p + 1], ah[mt], bl[2], bl[3]);
            }
        }
        cur_s = (cur_s == 2) ? 0 : cur_s + 1;
        nxt_s = (nxt_s == 2) ? 0 : nxt_s + 1;
    }

#pragma unroll
    for (int mt = 0; mt < 2; mt++) {
        const int mg = m0 + warp_m * 32 + mt * 16 + (lane >> 2);
#pragma unroll
        for (int nt = 0; nt < 8; nt++) {
            const int ng = n0 + warp_n * 64 + nt * 8 + 2 * (lane & 3);
            const float b0 = __ldg(qb + ng), b1 = __ldg(qb + ng + 1);
            *(float2*)(g_qm + (size_t)mg * 1024 + ng) =
                make_float2(c[mt][nt][0] + b0, c[mt][nt][1] + b1);
            *(float2*)(g_qm + (size_t)(mg + 8) * 1024 + ng) =
                make_float2(c[mt][nt][2] + b0, c[mt][nt][3] + b1);
        }
    }
}

// ---------------------------------------------------------------------------
// K3: fused attention, plain (no-max) softmax; cp.async 4-stage pipeline.
// ---------------------------------------------------------------------------
#define AT_L    0
#define AT_SS   65536
#define AT_RED  67456
#define AT_SMEM 67968

__global__ __launch_bounds__(256, 3) void k_attend(
    const float* __restrict__ x1, const float* __restrict__ x2,
    float* __restrict__ out)
{
    extern __shared__ __align__(16) unsigned char smem[];
    float4* s_L  = (float4*)(smem + AT_L);
    float (*s_s)[4] = (float (*)[4])(smem + AT_SS);
    float (*s_red)[16] = (float (*)[16])(smem + AT_RED);

    const int b = blockIdx.x;
    const int tid = threadIdx.x;
    const int w = tid >> 5, lane = tid & 31;
    const uint32 sL = (uint32)__cvta_generic_to_shared(s_L);

    const float* x1b = x1 + (size_t)b * NSEQ * FF;
    const float* x2b = x2 + (size_t)b * NSEQ * FF;
    const float4* qmg = (const float4*)(g_qm + (size_t)b * 4 * FF);

#define AT_ISSUE(bt)                                                          \
    {                                                                         \
        const int _st = (bt) & 3;                                             \
        _Pragma("unroll")                                                     \
        for (int _r = 0; _r < 4; _r++) {                                      \
            int _n = (bt) * 4 + _r;                                           \
            const float* _src = (_n < NSEQ) ? (x1b + (size_t)_n * FF)         \
                                            : (x2b + (size_t)(_n - NSEQ) * FF); \
            cpa16(sL + ((_st * 4 + _r) * 256 + tid) * 16, _src + 4 * tid);    \
        }                                                                     \
        asm volatile("cp.async.commit_group;");                               \
    }

    AT_ISSUE(0); AT_ISSUE(1); AT_ISSUE(2);

    float4 qm[4];
#pragma unroll
    for (int j = 0; j < 4; j++) qm[j] = qmg[j * 256 + tid];

    float4 o[4];
#pragma unroll
    for (int j = 0; j < 4; j++) o[j] = make_float4(0.f, 0.f, 0.f, 0.f);

    float l_run = 0.f;
    const float scale = 0.03125f;

    for (int bt = 0; bt < 30; bt++) {
        asm volatile("cp.async.wait_group 2;");
        __syncthreads();

        const int st = bt & 3;
        float4 rv[4];
#pragma unroll
        for (int r = 0; r < 4; r++) rv[r] = s_L[(st * 4 + r) * 256 + tid];

        if (bt + 3 < 30) { AT_ISSUE(bt + 3); }
        else { asm volatile("cp.async.commit_group;"); }

        float p[16];
#pragma unroll
        for (int r = 0; r < 4; r++)
#pragma unroll
            for (int j = 0; j < 4; j++) p[r * 4 + j] = dot4(rv[r], qm[j]);

#pragma unroll
        for (int v = 0; v < 16; v++) p[v] += __shfl_xor_sync(FULLW, p[v], 16);
        float q8[8];
#pragma unroll
        for (int v = 0; v < 8; v++) q8[v] = (lane & 16) ? p[v + 8] : p[v];
#pragma unroll
        for (int v = 0; v < 8; v++) q8[v] += __shfl_xor_sync(FULLW, q8[v], 8);
        float q4[4];
#pragma unroll
        for (int v = 0; v < 4; v++) q4[v] = (lane & 8) ? q8[v + 4] : q8[v];
#pragma unroll
        for (int v = 0; v < 4; v++) q4[v] += __shfl_xor_sync(FULLW, q4[v], 4);
        float q2[2];
#pragma unroll
        for (int v = 0; v < 2; v++) q2[v] = (lane & 4) ? q4[v + 2] : q4[v];
#pragma unroll
        for (int v = 0; v < 2; v++) q2[v] += __shfl_xor_sync(FULLW, q2[v], 2);
        float q1 = (lane & 2) ? q2[1] : q2[0];
        q1 += __shfl_xor_sync(FULLW, q1, 1);

        if (!(lane & 1)) s_red[w][lane >> 1] = q1;
        __syncthreads();

        float v16 = 0.f;
        if (lane < 16) {
#pragma unroll
            for (int ww = 0; ww < 8; ww++) v16 += s_red[ww][lane];
            v16 *= scale;
        }
        if (w == 0 && lane < 16) s_s[bt * 4 + (lane >> 2)][lane & 3] = v16;

        const int j = lane & 3;
        float t0 = __shfl_sync(FULLW, v16, j);
        float t1 = __shfl_sync(FULLW, v16, 4 + j);
        float t2 = __shfl_sync(FULLW, v16, 8 + j);
        float t3 = __shfl_sync(FULLW, v16, 12 + j);

        float w0 = __expf(t0);
        float w1 = __expf(t1);
        float w2 = __expf(t2);
        float w3 = __expf(t3);
        l_run += (w0 + w1) + (w2 + w3);

#pragma unroll
        for (int r = 0; r < 4; r++) {
            float wr = (r == 0) ? w0 : (r == 1) ? w1 : (r == 2) ? w2 : w3;
            float wa = __shfl_sync(FULLW, wr, 0);
            float wb = __shfl_sync(FULLW, wr, 1);
            float wc = __shfl_sync(FULLW, wr, 2);
            float wd = __shfl_sync(FULLW, wr, 3);
            o[0].x += wa * rv[r].x; o[0].y += wa * rv[r].y; o[0].z += wa * rv[r].z; o[0].w += wa * rv[r].w;
            o[1].x += wb * rv[r].x; o[1].y += wb * rv[r].y; o[1].z += wb * rv[r].z; o[1].w += wb * rv[r].w;
            o[2].x += wc * rv[r].x; o[2].y += wc * rv[r].y; o[2].z += wc * rv[r].z; o[2].w += wc * rv[r].w;
            o[3].x += wd * rv[r].x; o[3].y += wd * rv[r].y; o[3].z += wd * rv[r].z; o[3].w += wd * rv[r].w;
        }
    }
    __syncthreads();

    float linv[4];
#pragma unroll
    for (int j = 0; j < 4; j++) linv[j] = 1.f / __shfl_sync(FULLW, l_run, j);

#pragma unroll
    for (int j = 0; j < 4; j++) {
        float4 val;
        val.x = 0.9f * o[j].x * linv[j] + 0.1f * qm[j].x;
        val.y = 0.9f * o[j].y * linv[j] + 0.1f * qm[j].y;
        val.z = 0.9f * o[j].z * linv[j] + 0.1f * qm[j].z;
        val.w = 0.9f * o[j].w * linv[j] + 0.1f * qm[j].w;
        if (j < 2) {
            *(float4*)(out + OFF_O1 + ((size_t)b * 2 + j) * FF + 4 * tid) = val;
            *(float4*)(out + OFF_X + ((size_t)b * 2 + j) * 2048 + 4 * tid) = val;
        } else {
            *(float4*)(out + OFF_O2 + ((size_t)b * 2 + (j - 2)) * FF + 4 * tid) = val;
            *(float4*)(out + OFF_X + ((size_t)b * 2 + (j - 2)) * 2048 + 1024 + 4 * tid) = val;
        }
    }

    if (tid < NN) {
        int n = tid;
        float s0 = s_s[n][0], s1 = s_s[n][1], s2 = s_s[n][2], s3 = s_s[n][3];
        if (n < NSEQ) {
            out[OFF_ATT1 + (size_t)b * 60 + n] = __expf(s0) * linv[0];
            out[OFF_A11 + (size_t)b * 60 + n]  = __expf(s1) * linv[1];
            out[OFF_A21 + (size_t)b * 60 + n]  = __expf(s3) * linv[3];
        } else {
            int nn = n - NSEQ;
            out[OFF_ATT2 + (size_t)b * 60 + nn] = __expf(s2) * linv[2];
            out[OFF_A12 + (size_t)b * 60 + nn]  = __expf(s1) * linv[1];
            out[OFF_A22 + (size_t)b * 60 + nn]  = __expf(s3) * linv[3];
        }
    }
#undef AT_ISSUE
}

// ---------------------------------------------------------------------------
extern "C" void kernel_launch(void* const* d_in, const int* in_sizes, int n_in,
                              void* d_out, int out_size)
{
    (void)in_sizes; (void)n_in; (void)out_size;
    const float* x1   = (const float*)d_in[0];
    const float* x2   = (const float*)d_in[1];
    const float* fc_w = (const float*)d_in[2];
    // d_in[3] = fc_b (constant per class: doesn't change argmax over n)
    const float* q_w  = (const float*)d_in[4];
    const float* q_b  = (const float*)d_in[5];
    float* out = (float*)d_out;

    k_split_w<<<1024, 256>>>(q_w);

    dim3 g1(BB, 2);
    k_select<<<g1, 256>>>(x1, x2, fc_w, out);

    cudaFuncSetAttribute(k_qm_mma, cudaFuncAttributeMaxDynamicSharedMemorySize, QM_SMEM);
    dim3 g2(8, 32);   // (N/128, M/128)
    k_qm_mma<<<g2, 256, QM_SMEM>>>(q_b);

    cudaFuncSetAttribute(k_attend, cudaFuncAttributeMaxDynamicSharedMemorySize, AT_SMEM);
    k_attend<<<BB, 256, AT_SMEM>>>(x1, x2, out);
}